// round 14
// baseline (speedup 1.0000x reference)
#include <cuda_runtime.h>

// Problem shape (fixed by setup_inputs)
#define B_  256
#define T_  8192
#define TB  512          // timesteps per block (T_ % TB == 0)
#define NTH 256          // threads per block
#define NCHUNK (T_ / TB) // 16

// Illegal transition bitmask: pairs (0,2),(1,0),(2,0),(2,1) -> codes 2,3,6,7
#define ILLEGAL_MASK 0xCC

// Zero-initialized at module load; final_kernel resets after each read,
// so every kernel_launch call observes zeros (graph-replay safe).
__device__ double g_main = 0.0;
__device__ double g_csum = 0.0;
__device__ double g_ccnt = 0.0;

__device__ __forceinline__ float warp_sum(float v) {
    #pragma unroll
    for (int o = 16; o; o >>= 1) v += __shfl_down_sync(0xffffffffu, v, o);
    return v;
}

__global__ __launch_bounds__(NTH, 6)
void loss_kernel(const float* __restrict__ pred_robot,
                 const float* __restrict__ pred_phase,
                 const float* __restrict__ gt_robot,
                 const int*   __restrict__ gt_phase)
{
    // Robot rows padded to 13 floats: stride 13 coprime with 32 banks -> conflict-free.
    __shared__ float shR[(TB + 2) * 13];              // 26728 B
    __shared__ __align__(16) float shP[(TB + 1) * 3]; //  6156 B
    __shared__ float sred[3][8];

    const int b    = blockIdx.y;
    const int bx   = blockIdx.x;
    const int t0   = bx * TB;
    const int tid  = threadIdx.x;
    const bool has_halo = (bx < NCHUNK - 1);

    const long rbase = ((long)b * T_ + t0) * 12;
    const long pbase = ((long)b * T_ + t0) * 3;
    const float4* p4 = (const float4*)(pred_robot + rbase);
    const float4* g4 = (const float4*)(gt_robot   + rbase);
    const float4* h4 = (const float4*)(pred_phase + pbase);

    float racc = 0.f;

    // ---- Two half-tiles, each with front-batched loads (MLP ~ 8) ----
    #pragma unroll
    for (int h = 0; h < 2; h++) {
        const int base = h * 768;     // 256 rows * 3 float4 per half
        float4 p0 = p4[base + tid];
        float4 p1 = p4[base + tid + 256];
        float4 p2 = p4[base + tid + 512];
        float4 g0 = g4[base + tid];
        float4 g1 = g4[base + tid + 256];
        float4 g2 = g4[base + tid + 512];

        float dx, dy, dz, dw, s = 0.f;
        dx = p0.x - g0.x; dy = p0.y - g0.y; dz = p0.z - g0.z; dw = p0.w - g0.w;
        s += dx*dx + dy*dy + dz*dz + dw*dw;
        dx = p1.x - g1.x; dy = p1.y - g1.y; dz = p1.z - g1.z; dw = p1.w - g1.w;
        s += dx*dx + dy*dy + dz*dz + dw*dw;
        dx = p2.x - g2.x; dy = p2.y - g2.y; dz = p2.z - g2.z; dw = p2.w - g2.w;
        s += dx*dx + dy*dy + dz*dz + dw*dw;
        racc += s;

        int j, row, sp;
        j = base + tid;        row = j / 3; sp = row * 13 + (j - row * 3) * 4;
        shR[sp] = p0.x; shR[sp+1] = p0.y; shR[sp+2] = p0.z; shR[sp+3] = p0.w;
        j = base + tid + 256;  row = j / 3; sp = row * 13 + (j - row * 3) * 4;
        shR[sp] = p1.x; shR[sp+1] = p1.y; shR[sp+2] = p1.z; shR[sp+3] = p1.w;
        j = base + tid + 512;  row = j / 3; sp = row * 13 + (j - row * 3) * 4;
        shR[sp] = p2.x; shR[sp+1] = p2.y; shR[sp+2] = p2.z; shR[sp+3] = p2.w;
    }

    // ---- Robot halo rows TB, TB+1 (6 float4) ----
    if (has_halo && tid < 6) {
        float4 hr = p4[1536 + tid];
        int j = 1536 + tid, row = j / 3, sp = row * 13 + (j - row * 3) * 4;
        shR[sp] = hr.x; shR[sp+1] = hr.y; shR[sp+2] = hr.z; shR[sp+3] = hr.w;
    }
    // ---- Phase: 512 rows = 384 float4; + halo row TB ----
    {
        float4 ph0 = h4[tid];
        ((float4*)shP)[tid] = ph0;
        if (tid < 128) {
            float4 ph1 = h4[tid + 256];
            ((float4*)shP)[tid + 256] = ph1;
        }
        if (has_halo && tid == 0) {
            shP[1536] = pred_phase[pbase + 1536];
            shP[1537] = pred_phase[pbase + 1537];
            shP[1538] = pred_phase[pbase + 1538];
        }
    }
    const int gpa = gt_phase[(long)b * T_ + t0 + tid];
    const int gpb = gt_phase[(long)b * T_ + t0 + 256 + tid];

    // Allow the dependent finalize kernel to begin launching early (PDL).
    #if __CUDA_ARCH__ >= 900
    cudaTriggerProgrammaticLaunchCompletion();
    #endif
    __syncthreads();

    float pacc = 0.f, cacc = 0.f, ccnt = 0.f;
    float sacc = 0.f, vacc = 0.f, aacc = 0.f;

    // ---- Compute for two timesteps: tt = tid and tt = tid + 256 ----
    #pragma unroll
    for (int h = 0; h < 2; h++) {
        const int tt = tid + h * 256;
        const int t  = t0 + tt;
        const int gp = h ? gpb : gpa;

        // Phase NLL + coherence
        {
            float l0 = shP[tt*3], l1 = shP[tt*3+1], l2 = shP[tt*3+2];
            float m   = fmaxf(l0, fmaxf(l1, l2));
            float lse = m + __logf(__expf(l0 - m) + __expf(l1 - m) + __expf(l2 - m));
            float lg  = (gp == 0) ? l0 : ((gp == 1) ? l1 : l2);
            pacc += lse - lg;

            int pt = 0; float bm = l0;
            if (l1 > bm) { bm = l1; pt = 1; }
            if (l2 > bm) { pt = 2; }

            if (t + 1 < T_) {
                float n0 = shP[tt*3+3], n1 = shP[tt*3+4], n2 = shP[tt*3+5];
                int pt1 = 0; float sel = n0;
                if (n1 > sel) { sel = n1; pt1 = 1; }
                if (n2 > sel) { pt1 = 2; sel = n2; }
                int code = pt * 3 + pt1;
                if ((ILLEGAL_MASK >> code) & 1) { cacc += sel * sel; ccnt += 1.0f; }
            }
        }

        // Temporal robot terms — register diet: r0 dies into v,
        // acc uses (r2 - r1) - v  ==  r2 - 2*r1 + r0.
        {
            const int s0 = tt * 13;
            if (t + 1 < T_) {
                float r1[12], v[12];
                #pragma unroll
                for (int d = 0; d < 12; d++) {
                    r1[d] = shR[s0 + 13 + d];
                    v[d]  = r1[d] - shR[s0 + d];
                    vacc += v[d] * v[d];
                }
                #pragma unroll
                for (int k = 0; k < 4; k++) {
                    float sp2 = v[3*k]*v[3*k] + v[3*k+1]*v[3*k+1] + v[3*k+2]*v[3*k+2];
                    float pen = fmaxf(sqrtf(sp2) - 10.0f, 0.0f);
                    sacc += pen * pen;
                }
                if (t + 2 < T_) {
                    #pragma unroll
                    for (int d = 0; d < 12; d++) {
                        float a = (shR[s0 + 26 + d] - r1[d]) - v[d];
                        aacc += a * a;
                    }
                }
            }
        }
    }

    // ---- Fold 5 constant-normalized terms into one weighted value ----
    const float W_R = 1.0f   / ((float)B_ * T_ * 12);
    const float W_P = 1.0f   / ((float)B_ * T_);
    const float W_S = 5.0f   / ((float)B_ * (T_ - 1) * 4);
    const float W_V = 0.05f  / ((float)B_ * (T_ - 1) * 12);
    const float W_A = 0.01f  / ((float)B_ * (T_ - 2) * 12);
    float wmain = racc * W_R + pacc * W_P + sacc * W_S + vacc * W_V + aacc * W_A;

    // ---- Block reduction: 3 values -> 3 double atomics ----
    float vals[3] = {wmain, cacc, ccnt};
    const int lane = tid & 31, wid = tid >> 5;
    #pragma unroll
    for (int i = 0; i < 3; i++) {
        float w = warp_sum(vals[i]);
        if (lane == 0) sred[i][wid] = w;
    }
    __syncthreads();
    if (tid == 0) {
        float v0 = 0.f, v1 = 0.f, v2 = 0.f;
        #pragma unroll
        for (int i = 0; i < 8; i++) {
            v0 += sred[0][i]; v1 += sred[1][i]; v2 += sred[2][i];
        }
        atomicAdd(&g_main, (double)v0);
        atomicAdd(&g_csum, (double)v1);
        atomicAdd(&g_ccnt, (double)v2);
    }
}

__global__ void final_kernel(float* __restrict__ out) {
    // Under PDL this kernel is resident early; wait until the full loss grid
    // (and its memory) is complete before reading the accumulators.
    #if __CUDA_ARCH__ >= 900
    cudaGridDependencySynchronize();
    #endif
    double coher = (g_ccnt > 0.0) ? (g_csum / g_ccnt) : 0.0;
    out[0] = (float)(g_main + 10.0 * coher);
    // Reset for the next invocation (globals start zero at module load).
    g_main = 0.0; g_csum = 0.0; g_ccnt = 0.0;
}

extern "C" void kernel_launch(void* const* d_in, const int* in_sizes, int n_in,
                              void* d_out, int out_size)
{
    const float* pred_robot = (const float*)d_in[0];
    const float* pred_phase = (const float*)d_in[1];
    const float* gt_robot   = (const float*)d_in[2];
    const int*   gt_phase   = (const int*)  d_in[3];

    dim3 grid(NCHUNK, B_);   // (16, 256) = 4096 blocks
    loss_kernel<<<grid, NTH>>>(pred_robot, pred_phase, gt_robot, gt_phase);

    // Finalize with programmatic dependent launch so its launch latency
    // overlaps the loss kernel's drain. Fall back to a plain launch if the
    // PDL attribute is rejected (e.g., unsupported under capture).
    cudaLaunchConfig_t cfg = {};
    cfg.gridDim  = dim3(1, 1, 1);
    cfg.blockDim = dim3(1, 1, 1);
    cfg.dynamicSmemBytes = 0;
    cfg.stream = 0;
    cudaLaunchAttribute attrs[1];
    attrs[0].id = cudaLaunchAttributeProgrammaticStreamSerialization;
    attrs[0].val.programmaticStreamSerializationAllowed = 1;
    cfg.attrs = attrs;
    cfg.numAttrs = 1;
    cudaError_t e = cudaLaunchKernelEx(&cfg, final_kernel, (float*)d_out);
    if (e != cudaSuccess) {
        (void)cudaGetLastError();
        final_kernel<<<1, 1>>>((float*)d_out);
    }
}

// round 17
// speedup vs baseline: 1.1830x; 1.1830x over previous
#include <cuda_runtime.h>

// Problem shape (fixed by setup_inputs)
#define B_  256
#define T_  8192
#define TB  512          // timesteps per block (T_ % TB == 0)
#define NTH 256          // threads per block
#define NCHUNK (T_ / TB) // 16

// Illegal transition bitmask: pairs (0,2),(1,0),(2,0),(2,1) -> codes 2,3,6,7
#define ILLEGAL_MASK 0xCC

// Zero-initialized at module load; final_kernel resets after each read,
// so every kernel_launch call observes zeros (graph-replay safe).
__device__ double g_main = 0.0;
__device__ double g_csum = 0.0;
__device__ double g_ccnt = 0.0;

__device__ __forceinline__ float warp_sum(float v) {
    #pragma unroll
    for (int o = 16; o; o >>= 1) v += __shfl_down_sync(0xffffffffu, v, o);
    return v;
}

__global__ __launch_bounds__(NTH, 5)
void loss_kernel(const float* __restrict__ pred_robot,
                 const float* __restrict__ pred_phase,
                 const float* __restrict__ gt_robot,
                 const int*   __restrict__ gt_phase)
{
    // Robot rows padded to 13 floats: stride 13 coprime with 32 banks -> conflict-free.
    __shared__ float shR[(TB + 2) * 13];              // 26728 B
    __shared__ __align__(16) float shP[(TB + 1) * 3]; //  6156 B
    __shared__ float sred[3][8];

    const int b    = blockIdx.y;
    const int bx   = blockIdx.x;
    const int t0   = bx * TB;
    const int tid  = threadIdx.x;
    const bool has_halo = (bx < NCHUNK - 1);

    const long rbase = ((long)b * T_ + t0) * 12;
    const long pbase = ((long)b * T_ + t0) * 3;
    const float4* p4 = (const float4*)(pred_robot + rbase);
    const float4* g4 = (const float4*)(gt_robot   + rbase);
    const float4* h4 = (const float4*)(pred_phase + pbase);

    float racc = 0.f;

    // ---- Half-tile 0: front-batched robot loads (MLP ~ 8) ----
    {
        float4 p0 = p4[tid];
        float4 p1 = p4[tid + 256];
        float4 p2 = p4[tid + 512];
        float4 g0 = g4[tid];
        float4 g1 = g4[tid + 256];
        float4 g2 = g4[tid + 512];

        float dx, dy, dz, dw, s = 0.f;
        dx = p0.x - g0.x; dy = p0.y - g0.y; dz = p0.z - g0.z; dw = p0.w - g0.w;
        s += dx*dx + dy*dy + dz*dz + dw*dw;
        dx = p1.x - g1.x; dy = p1.y - g1.y; dz = p1.z - g1.z; dw = p1.w - g1.w;
        s += dx*dx + dy*dy + dz*dz + dw*dw;
        dx = p2.x - g2.x; dy = p2.y - g2.y; dz = p2.z - g2.z; dw = p2.w - g2.w;
        s += dx*dx + dy*dy + dz*dz + dw*dw;
        racc += s;

        int j, row, sp;
        j = tid;        row = j / 3; sp = row * 13 + (j - row * 3) * 4;
        shR[sp] = p0.x; shR[sp+1] = p0.y; shR[sp+2] = p0.z; shR[sp+3] = p0.w;
        j = tid + 256;  row = j / 3; sp = row * 13 + (j - row * 3) * 4;
        shR[sp] = p1.x; shR[sp+1] = p1.y; shR[sp+2] = p1.z; shR[sp+3] = p1.w;
        j = tid + 512;  row = j / 3; sp = row * 13 + (j - row * 3) * 4;
        shR[sp] = p2.x; shR[sp+1] = p2.y; shR[sp+2] = p2.z; shR[sp+3] = p2.w;
    }

    // ---- Phase + gt_phase loads issued HERE so their DRAM latency overlaps
    //      half-1's load/store stream instead of serializing after it ----
    float4 ph0 = h4[tid];
    float4 ph1 = (tid < 128) ? h4[tid + 256] : make_float4(0.f,0.f,0.f,0.f);
    const int gpa = gt_phase[(long)b * T_ + t0 + tid];
    const int gpb = gt_phase[(long)b * T_ + t0 + 256 + tid];

    // ---- Half-tile 1 ----
    {
        float4 p0 = p4[768 + tid];
        float4 p1 = p4[768 + tid + 256];
        float4 p2 = p4[768 + tid + 512];
        float4 g0 = g4[768 + tid];
        float4 g1 = g4[768 + tid + 256];
        float4 g2 = g4[768 + tid + 512];

        float dx, dy, dz, dw, s = 0.f;
        dx = p0.x - g0.x; dy = p0.y - g0.y; dz = p0.z - g0.z; dw = p0.w - g0.w;
        s += dx*dx + dy*dy + dz*dz + dw*dw;
        dx = p1.x - g1.x; dy = p1.y - g1.y; dz = p1.z - g1.z; dw = p1.w - g1.w;
        s += dx*dx + dy*dy + dz*dz + dw*dw;
        dx = p2.x - g2.x; dy = p2.y - g2.y; dz = p2.z - g2.z; dw = p2.w - g2.w;
        s += dx*dx + dy*dy + dz*dz + dw*dw;
        racc += s;

        int j, row, sp;
        j = 768 + tid;        row = j / 3; sp = row * 13 + (j - row * 3) * 4;
        shR[sp] = p0.x; shR[sp+1] = p0.y; shR[sp+2] = p0.z; shR[sp+3] = p0.w;
        j = 768 + tid + 256;  row = j / 3; sp = row * 13 + (j - row * 3) * 4;
        shR[sp] = p1.x; shR[sp+1] = p1.y; shR[sp+2] = p1.z; shR[sp+3] = p1.w;
        j = 768 + tid + 512;  row = j / 3; sp = row * 13 + (j - row * 3) * 4;
        shR[sp] = p2.x; shR[sp+1] = p2.y; shR[sp+2] = p2.z; shR[sp+3] = p2.w;
    }

    // ---- Robot halo rows TB, TB+1 (6 float4) ----
    if (has_halo && tid < 6) {
        float4 hr = p4[1536 + tid];
        int j = 1536 + tid, row = j / 3, sp = row * 13 + (j - row * 3) * 4;
        shR[sp] = hr.x; shR[sp+1] = hr.y; shR[sp+2] = hr.z; shR[sp+3] = hr.w;
    }
    // ---- Phase stores + halo row TB ----
    {
        ((float4*)shP)[tid] = ph0;
        if (tid < 128) ((float4*)shP)[tid + 256] = ph1;
        if (has_halo && tid == 0) {
            shP[1536] = pred_phase[pbase + 1536];
            shP[1537] = pred_phase[pbase + 1537];
            shP[1538] = pred_phase[pbase + 1538];
        }
    }

    // Allow the dependent finalize kernel to begin launching early (PDL).
    #if __CUDA_ARCH__ >= 900
    cudaTriggerProgrammaticLaunchCompletion();
    #endif
    __syncthreads();

    float pacc = 0.f, cacc = 0.f, ccnt = 0.f;
    float sacc = 0.f, vacc = 0.f, aacc = 0.f;

    // ---- Compute for two timesteps: tt = tid and tt = tid + 256 ----
    #pragma unroll
    for (int h = 0; h < 2; h++) {
        const int tt = tid + h * 256;
        const int t  = t0 + tt;
        const int gp = h ? gpb : gpa;

        // Phase NLL + coherence
        {
            float l0 = shP[tt*3], l1 = shP[tt*3+1], l2 = shP[tt*3+2];
            float m   = fmaxf(l0, fmaxf(l1, l2));
            float lse = m + __logf(__expf(l0 - m) + __expf(l1 - m) + __expf(l2 - m));
            float lg  = (gp == 0) ? l0 : ((gp == 1) ? l1 : l2);
            pacc += lse - lg;

            int pt = 0; float bm = l0;
            if (l1 > bm) { bm = l1; pt = 1; }
            if (l2 > bm) { pt = 2; }

            if (t + 1 < T_) {
                float n0 = shP[tt*3+3], n1 = shP[tt*3+4], n2 = shP[tt*3+5];
                int pt1 = 0; float sel = n0;
                if (n1 > sel) { sel = n1; pt1 = 1; }
                if (n2 > sel) { pt1 = 2; sel = n2; }
                int code = pt * 3 + pt1;
                if ((ILLEGAL_MASK >> code) & 1) { cacc += sel * sel; ccnt += 1.0f; }
            }
        }

        // Temporal robot terms — register diet: r0 dies into v,
        // acc uses (r2 - r1) - v  ==  r2 - 2*r1 + r0.
        {
            const int s0 = tt * 13;
            if (t + 1 < T_) {
                float r1[12], v[12];
                #pragma unroll
                for (int d = 0; d < 12; d++) {
                    r1[d] = shR[s0 + 13 + d];
                    v[d]  = r1[d] - shR[s0 + d];
                    vacc += v[d] * v[d];
                }
                #pragma unroll
                for (int k = 0; k < 4; k++) {
                    float sp2 = v[3*k]*v[3*k] + v[3*k+1]*v[3*k+1] + v[3*k+2]*v[3*k+2];
                    float pen = fmaxf(sqrtf(sp2) - 10.0f, 0.0f);
                    sacc += pen * pen;
                }
                if (t + 2 < T_) {
                    #pragma unroll
                    for (int d = 0; d < 12; d++) {
                        float a = (shR[s0 + 26 + d] - r1[d]) - v[d];
                        aacc += a * a;
                    }
                }
            }
        }
    }

    // ---- Fold 5 constant-normalized terms into one weighted value ----
    const float W_R = 1.0f   / ((float)B_ * T_ * 12);
    const float W_P = 1.0f   / ((float)B_ * T_);
    const float W_S = 5.0f   / ((float)B_ * (T_ - 1) * 4);
    const float W_V = 0.05f  / ((float)B_ * (T_ - 1) * 12);
    const float W_A = 0.01f  / ((float)B_ * (T_ - 2) * 12);
    float wmain = racc * W_R + pacc * W_P + sacc * W_S + vacc * W_V + aacc * W_A;

    // ---- Block reduction: 3 values -> 3 double atomics ----
    float vals[3] = {wmain, cacc, ccnt};
    const int lane = tid & 31, wid = tid >> 5;
    #pragma unroll
    for (int i = 0; i < 3; i++) {
        float w = warp_sum(vals[i]);
        if (lane == 0) sred[i][wid] = w;
    }
    __syncthreads();
    if (tid == 0) {
        float v0 = 0.f, v1 = 0.f, v2 = 0.f;
        #pragma unroll
        for (int i = 0; i < 8; i++) {
            v0 += sred[0][i]; v1 += sred[1][i]; v2 += sred[2][i];
        }
        atomicAdd(&g_main, (double)v0);
        atomicAdd(&g_csum, (double)v1);
        atomicAdd(&g_ccnt, (double)v2);
    }
}

__global__ void final_kernel(float* __restrict__ out) {
    // Under PDL this kernel is resident early; wait until the full loss grid
    // (and its memory) is complete before reading the accumulators.
    #if __CUDA_ARCH__ >= 900
    cudaGridDependencySynchronize();
    #endif
    double coher = (g_ccnt > 0.0) ? (g_csum / g_ccnt) : 0.0;
    out[0] = (float)(g_main + 10.0 * coher);
    // Reset for the next invocation (globals start zero at module load).
    g_main = 0.0; g_csum = 0.0; g_ccnt = 0.0;
}

extern "C" void kernel_launch(void* const* d_in, const int* in_sizes, int n_in,
                              void* d_out, int out_size)
{
    const float* pred_robot = (const float*)d_in[0];
    const float* pred_phase = (const float*)d_in[1];
    const float* gt_robot   = (const float*)d_in[2];
    const int*   gt_phase   = (const int*)  d_in[3];

    dim3 grid(NCHUNK, B_);   // (16, 256) = 4096 blocks
    loss_kernel<<<grid, NTH>>>(pred_robot, pred_phase, gt_robot, gt_phase);

    // Finalize with programmatic dependent launch so its launch latency
    // overlaps the loss kernel's drain. Fall back to a plain launch if the
    // PDL attribute is rejected (e.g., unsupported under capture).
    cudaLaunchConfig_t cfg = {};
    cfg.gridDim  = dim3(1, 1, 1);
    cfg.blockDim = dim3(1, 1, 1);
    cfg.dynamicSmemBytes = 0;
    cfg.stream = 0;
    cudaLaunchAttribute attrs[1];
    attrs[0].id = cudaLaunchAttributeProgrammaticStreamSerialization;
    attrs[0].val.programmaticStreamSerializationAllowed = 1;
    cfg.attrs = attrs;
    cfg.numAttrs = 1;
    cudaError_t e = cudaLaunchKernelEx(&cfg, final_kernel, (float*)d_out);
    if (e != cudaSuccess) {
        (void)cudaGetLastError();
        final_kernel<<<1, 1>>>((float*)d_out);
    }
}